// round 4
// baseline (speedup 1.0000x reference)
#include <cuda_runtime.h>
#include <math.h>

// Problem constants
#define LNUM 196      // H*W
#define BTN  128      // B*T
#define DIM  768
#define NDH  64
#define NT   8
#define NB   16
#define NH   14
#define NLW  5
#define NROWS 25088   // LNUM*BTN
#define NF   640      // B*T*Lw frames
#define PIXC 15876    // 196*81

// ---------------- scratch (device globals: allocation-free) ----------------
__device__ float g_mu[NROWS];
__device__ float g_rstd[NROWS];
__device__ float g_Wg[NDH * DIM];
__device__ float g_A[NDH];
__device__ float g_Bc[NDH];
__device__ float g_fn[BTN * LNUM * NDH];          // normalized features [bt][pix][c]
__device__ float g_corr[(size_t)NF * PIXC];        // [frame][pix][81]
__device__ float g_yext[80 * 64 * 8 * 196];        // [(b*5+l)*64+c][t][pix]
__device__ float g_y0[80 * 64 * 8 * 196];
__device__ float g_y1[80 * 64 * 8 * 196];
__device__ float g_y2[16 * 64 * 8 * 196];          // [(b*64+c)][t][pix]
__device__ float g_y2t[(size_t)NROWS * 64];        // [(pix*128+bt)][c]

__device__ __forceinline__ float gelu_exact(float x) {
    return 0.5f * x * (1.0f + erff(x * 0.70710678118654752f));
}

// ---------------- kernel 0: fold layernorm gamma/beta into projection ------
__global__ void prep_w_kernel(const float* __restrict__ in_w,
                              const float* __restrict__ gamma,
                              const float* __restrict__ beta,
                              const float* __restrict__ in_b) {
    int c = blockIdx.x;
    int tid = threadIdx.x;
    float pa = 0.f, pb = 0.f;
    for (int d = tid; d < DIM; d += 256) {
        float w  = in_w[c * DIM + d];
        float wg = w * gamma[d];
        g_Wg[c * DIM + d] = wg;
        pa += wg;
        pb += w * beta[d];
    }
    __shared__ float rA[256], rB[256];
    rA[tid] = pa; rB[tid] = pb;
    __syncthreads();
    for (int s = 128; s > 0; s >>= 1) {
        if (tid < s) { rA[tid] += rA[tid + s]; rB[tid] += rB[tid + s]; }
        __syncthreads();
    }
    if (tid == 0) { g_A[c] = rA[0]; g_Bc[c] = rB[0] + in_b[c]; }
}

// ---------------- kernel 1: per-row LN stats -------------------------------
__global__ void rowstats_kernel(const float* __restrict__ x) {
    int w = threadIdx.x >> 5, lane = threadIdx.x & 31;
    int row = blockIdx.x * 8 + w;
    const float4* p = (const float4*)(x + (size_t)row * DIM);
    float s = 0.f, sq = 0.f;
#pragma unroll
    for (int i = 0; i < 6; i++) {
        float4 v = p[lane + i * 32];
        s  += v.x + v.y + v.z + v.w;
        sq += v.x * v.x + v.y * v.y + v.z * v.z + v.w * v.w;
    }
    for (int o = 16; o > 0; o >>= 1) {
        s  += __shfl_xor_sync(0xffffffffu, s,  o);
        sq += __shfl_xor_sync(0xffffffffu, sq, o);
    }
    if (lane == 0) {
        float mu  = s * (1.0f / DIM);
        float var = sq * (1.0f / DIM) - mu * mu;
        g_mu[row]   = mu;
        g_rstd[row] = rsqrtf(var + 1e-5f);
    }
}

// ---------------- kernel 2: input GEMM + LN epilogue + channel-normalize ---
__global__ void gemm_in_kernel(const float* __restrict__ x) {
    __shared__ float Xs[64][33];
    __shared__ float Ws[64][33];
    __shared__ float Sv[64][65];
    __shared__ float Srow[64][4];
    __shared__ float Sinv[64];
    int tid = threadIdx.x;
    int ty = tid >> 4, tx = tid & 15;
    int row0 = blockIdx.x * 64;
    float acc[4][4] = {};
    for (int kb = 0; kb < DIM; kb += 32) {
#pragma unroll
        for (int i = 0; i < 8; i++) {
            int e = tid + i * 256;
            int r = e >> 5, k = e & 31;
            Xs[r][k] = x[(size_t)(row0 + r) * DIM + kb + k];
            Ws[r][k] = g_Wg[r * DIM + kb + k];
        }
        __syncthreads();
#pragma unroll 8
        for (int k = 0; k < 32; k++) {
            float a[4], b[4];
#pragma unroll
            for (int i = 0; i < 4; i++) a[i] = Xs[ty * 4 + i][k];
#pragma unroll
            for (int j = 0; j < 4; j++) b[j] = Ws[tx * 4 + j][k];
#pragma unroll
            for (int i = 0; i < 4; i++)
#pragma unroll
                for (int j = 0; j < 4; j++) acc[i][j] += a[i] * b[j];
        }
        __syncthreads();
    }
    // LN epilogue: h0 = rs*acc - rs*mu*A + B
#pragma unroll
    for (int i = 0; i < 4; i++) {
        int r = row0 + ty * 4 + i;
        float rs = g_rstd[r], mu = g_mu[r];
#pragma unroll
        for (int j = 0; j < 4; j++) {
            int c = tx * 4 + j;
            Sv[ty * 4 + i][c] = rs * acc[i][j] - rs * mu * g_A[c] + g_Bc[c];
        }
    }
    __syncthreads();
    {   // row-wise sum of squares (4 threads per row)
        int row = tid >> 2, q = tid & 3;
        float s = 0.f;
#pragma unroll
        for (int c = 0; c < 16; c++) { float v = Sv[row][q * 16 + c]; s += v * v; }
        Srow[row][q] = s;
    }
    __syncthreads();
    if (tid < 64) {
        float n = Srow[tid][0] + Srow[tid][1] + Srow[tid][2] + Srow[tid][3];
        Sinv[tid] = 1.0f / fmaxf(sqrtf(n), 1e-7f);
    }
    __syncthreads();
#pragma unroll
    for (int i = 0; i < 16; i++) {
        int e = tid + i * 256;
        int row = e >> 6, c = e & 63;
        int r = row0 + row;
        int l = r >> 7, bt = r & 127;   // r = pix*128 + bt
        g_fn[((size_t)bt * LNUM + l) * NDH + c] = Sv[row][c] * Sinv[row];
    }
}

// ---------------- kernel 3: local 9x9 correlation --------------------------
// grid = 640 frames (b,t,l); block = 224; dyn smem = tgt frame [64][196]
__global__ void corr_kernel() {
    extern __shared__ float s_tgt[];
    int fidx = blockIdx.x;
    int b = fidx / 40, rem = fidx % 40;
    int t = rem / 5, l = rem % 5;
    int ttg = t + l - 2;
    float* outp = g_corr + (size_t)fidx * PIXC;
    int tid = threadIdx.x;
    if (ttg < 0 || ttg >= NT) {              // temporal zero-pad
        for (int e = tid; e < PIXC; e += 224) outp[e] = 0.0f;
        return;
    }
    const float* tgt = g_fn + (size_t)(b * 8 + ttg) * (196 * 64);
    // load + transpose target frame -> [c][pix]
    for (int e = tid; e < 3136; e += 224) {
        int p = e >> 4, c4 = e & 15;
        float4 v = *(const float4*)(tgt + p * 64 + c4 * 4);
        s_tgt[(c4 * 4 + 0) * 196 + p] = v.x;
        s_tgt[(c4 * 4 + 1) * 196 + p] = v.y;
        s_tgt[(c4 * 4 + 2) * 196 + p] = v.z;
        s_tgt[(c4 * 4 + 3) * 196 + p] = v.w;
    }
    __syncthreads();
    if (tid < 196) {
        int h = tid / 14, w = tid % 14;
        const float4* src = (const float4*)(g_fn + ((size_t)(b * 8 + t) * 196 + tid) * 64);
        float s[64];
#pragma unroll
        for (int i = 0; i < 16; i++) {
            float4 v = src[i];
            s[i * 4 + 0] = v.x; s[i * 4 + 1] = v.y; s[i * 4 + 2] = v.z; s[i * 4 + 3] = v.w;
        }
        float* op = outp + tid * 81;
#pragma unroll 1
        for (int du = 0; du < 9; du++) {
            int uh = h + du - 4;
            bool rok = (uh >= 0) && (uh < 14);
#pragma unroll 1
            for (int dv = 0; dv < 9; dv++) {
                int vw = w + dv - 4;
                float acc = 0.0f;
                if (rok && vw >= 0 && vw < 14) {
                    const float* tp = s_tgt + uh * 14 + vw;
#pragma unroll
                    for (int c = 0; c < 64; c++) acc += s[c] * tp[c * 196];
                }
                op[du * 9 + dv] = acc;
            }
        }
    }
}

// ---------------- kernel 4: ext 1x1 (81->64) + BN + GELU -------------------
// grid (640 frames, 4 pixel-chunks of 49), block 256
__global__ void ext_kernel(const float* __restrict__ ew,
                           const float* __restrict__ scale,
                           const float* __restrict__ shift) {
    __shared__ float sw[64 * 81];
    __shared__ float sc[49 * 81];
    int fidx = blockIdx.x;
    int pix0 = blockIdx.y * 49;
    int b = fidx / 40, rem = fidx % 40, t = rem / 5, l = rem % 5;
    int tid = threadIdx.x;
    for (int e = tid; e < 5184; e += 256) sw[e] = ew[e];
    const float* cp = g_corr + (size_t)fidx * PIXC + (size_t)pix0 * 81;
    for (int e = tid; e < 3969; e += 256) sc[e] = cp[e];
    __syncthreads();
    size_t obase = ((size_t)(b * 5 + l) * 64) * 1568 + (size_t)t * 196 + pix0;
    for (int e = tid; e < 3136; e += 256) {
        int pl = e >> 6, co = e & 63;
        const float* wv = sw + co * 81;
        const float* cv = sc + pl * 81;
        float acc = 0.f;
#pragma unroll
        for (int k = 0; k < 81; k++) acc += wv[k] * cv[k];
        float v = acc * scale[co] + shift[co];
        g_yext[obase + (size_t)co * 1568 + pl] = gelu_exact(v);
    }
}

// ---------------- kernels 5/6: 3x3 conv (64ch in), 4px x 4co reg tile ------
// grid 640 (f80 x t), block 224, dyn smem = in[64][16][16] + w[16*64*9]
template <int WHICH>   // 0: yext->y0 (i0), 1: y0->y1 (i1)
__global__ void conv64_kernel(const float* __restrict__ W,
                              const float* __restrict__ scale,
                              const float* __restrict__ shift) {
    extern __shared__ float sm[];
    float* s_in = sm;           // 16384 floats
    float* s_w  = sm + 16384;   // 9216 floats
    const float* in = (WHICH == 0) ? g_yext : g_y0;
    float* out      = (WHICH == 0) ? g_y0   : g_y1;
    int f = blockIdx.x >> 3, t = blockIdx.x & 7;
    int tid = threadIdx.x;
    const float* inb = in + (size_t)(f * 512 + t) * 196;
    for (int e = tid; e < 16384; e += 224) s_in[e] = 0.0f;
    __syncthreads();
    for (int e = tid; e < 12544; e += 224) {
        int c = e / 196, p = e % 196;
        s_in[c * 256 + ((p / 14) + 1) * 16 + (p % 14) + 1] = inb[(size_t)c * 1568 + p];
    }
    __syncthreads();
    bool act = tid < 196;
    int cog = tid / 49, pxg = tid % 49;
    int bo[4];
    if (act) {
#pragma unroll
        for (int pp = 0; pp < 4; pp++) { int p = pxg * 4 + pp; bo[pp] = (p / 14) * 16 + (p % 14); }
    }
    float* ob = out + (size_t)(f * 512 + t) * 196;
    for (int cc = 0; cc < 4; cc++) {
        for (int e = tid; e < 9216; e += 224) {
            int col = e / 576, r = e % 576, ci = r / 9, tap = r % 9;
            s_w[e] = W[((cc * 16 + col) * 64 + ci) * 9 + tap];
        }
        __syncthreads();
        if (act) {
            float acc[4][4] = {};
#pragma unroll 2
            for (int ci = 0; ci < 64; ci++) {
                float wr[4][9];
                const float* wb = s_w + ci * 9;
#pragma unroll
                for (int j = 0; j < 4; j++)
#pragma unroll
                    for (int tap = 0; tap < 9; tap++)
                        wr[j][tap] = wb[(cog * 4 + j) * 576 + tap];
                const float* sp = s_in + ci * 256;
#pragma unroll
                for (int dh = 0; dh < 3; dh++)
#pragma unroll
                    for (int dw = 0; dw < 3; dw++) {
                        int off = dh * 16 + dw, tap = dh * 3 + dw;
                        float iv[4];
#pragma unroll
                        for (int pp = 0; pp < 4; pp++) iv[pp] = sp[bo[pp] + off];
#pragma unroll
                        for (int pp = 0; pp < 4; pp++)
#pragma unroll
                            for (int j = 0; j < 4; j++)
                                acc[pp][j] += iv[pp] * wr[j][tap];
                    }
            }
#pragma unroll
            for (int j = 0; j < 4; j++) {
                int co = cc * 16 + cog * 4 + j;
                float scv = scale[co], shv = shift[co];
#pragma unroll
                for (int pp = 0; pp < 4; pp++)
                    ob[(size_t)co * 1568 + pxg * 4 + pp] = gelu_exact(acc[pp][j] * scv + shv);
            }
        }
        __syncthreads();
    }
}

// ---------------- kernel 7: i2 3x3 conv, 320 in-ch -> 64 out-ch ------------
// grid (128 slices, 4 co-chunks), block 224; accumulators persist over 5 cin chunks
__global__ void conv320_kernel(const float* __restrict__ W,
                               const float* __restrict__ scale,
                               const float* __restrict__ shift) {
    extern __shared__ float sm[];
    float* s_in = sm;
    float* s_w  = sm + 16384;
    int slice = blockIdx.x;
    int b = slice >> 3, t = slice & 7;
    int cc = blockIdx.y;
    int tid = threadIdx.x;
    bool act = tid < 196;
    int cog = tid / 49, pxg = tid % 49;
    int bo[4];
    if (act) {
#pragma unroll
        for (int pp = 0; pp < 4; pp++) { int p = pxg * 4 + pp; bo[pp] = (p / 14) * 16 + (p % 14); }
    }
    float acc[4][4] = {};
    for (int cb = 0; cb < 5; cb++) {
        __syncthreads();    // prior compute must be done before smem reuse
        for (int e = tid; e < 16384; e += 224) s_in[e] = 0.0f;
        __syncthreads();
        for (int e = tid; e < 12544; e += 224) {
            int ci = e / 196, p = e % 196;
            s_in[ci * 256 + ((p / 14) + 1) * 16 + (p % 14) + 1] =
                g_y1[(size_t)((b * 320 + cb * 64 + ci) * 8 + t) * 196 + p];
        }
        for (int e = tid; e < 9216; e += 224) {
            int col = e / 576, r = e % 576, ci = r / 9, tap = r % 9;
            s_w[e] = W[((cc * 16 + col) * 320 + cb * 64 + ci) * 9 + tap];
        }
        __syncthreads();
        if (act) {
#pragma unroll 2
            for (int ci = 0; ci < 64; ci++) {
                float wr[4][9];
                const float* wb = s_w + ci * 9;
#pragma unroll
                for (int j = 0; j < 4; j++)
#pragma unroll
                    for (int tap = 0; tap < 9; tap++)
                        wr[j][tap] = wb[(cog * 4 + j) * 576 + tap];
                const float* sp = s_in + ci * 256;
#pragma unroll
                for (int dh = 0; dh < 3; dh++)
#pragma unroll
                    for (int dw = 0; dw < 3; dw++) {
                        int off = dh * 16 + dw, tap = dh * 3 + dw;
                        float iv[4];
#pragma unroll
                        for (int pp = 0; pp < 4; pp++) iv[pp] = sp[bo[pp] + off];
#pragma unroll
                        for (int pp = 0; pp < 4; pp++)
#pragma unroll
                            for (int j = 0; j < 4; j++)
                                acc[pp][j] += iv[pp] * wr[j][tap];
                    }
            }
        }
    }
    if (act) {
        float* ob = g_y2 + (size_t)(b * 512 + t) * 196;
#pragma unroll
        for (int j = 0; j < 4; j++) {
            int co = cc * 16 + cog * 4 + j;
            float scv = scale[co], shv = shift[co];
#pragma unroll
            for (int pp = 0; pp < 4; pp++)
                ob[(size_t)co * 1568 + pxg * 4 + pp] = gelu_exact(acc[pp][j] * scv + shv);
        }
    }
}

// ---------------- kernel 8: transpose y2 -> row-major [(pix,bt)][c] --------
__global__ void transpose_y2_kernel() {
    int e = blockIdx.x * 256 + threadIdx.x;   // 16*64*8*196 = 1,605,632 exact
    float v = g_y2[e];
    int pix = e % 196;
    int t = (e / 196) & 7;
    int c = (e / 1568) & 63;
    int b = e / (1568 * 64);
    g_y2t[((size_t)(pix * 128 + b * 8 + t)) * 64 + c] = v;
}

// ---------------- kernel 9: output GEMM (25088 x 64 -> 768) + bias ---------
__global__ void gemm_out_kernel(const float* __restrict__ Wo,
                                const float* __restrict__ bvec,
                                float* __restrict__ out) {
    __shared__ float Ys[64][65];
    __shared__ float Wsm[64][65];
    int tid = threadIdx.x;
    int row0 = blockIdx.x * 64, col0 = blockIdx.y * 64;
#pragma unroll
    for (int i = 0; i < 16; i++) {
        int e = tid + i * 256;
        int r = e >> 6, k = e & 63;
        Ys[r][k]  = g_y2t[(size_t)(row0 + r) * 64 + k];
        Wsm[r][k] = Wo[(size_t)(col0 + r) * 64 + k];
    }
    __syncthreads();
    int ty = tid >> 4, tx = tid & 15;
    float acc[4][4] = {};
#pragma unroll 8
    for (int k = 0; k < 64; k++) {
        float a[4], bv[4];
#pragma unroll
        for (int i = 0; i < 4; i++) a[i] = Ys[ty * 4 + i][k];
#pragma unroll
        for (int j = 0; j < 4; j++) bv[j] = Wsm[tx * 4 + j][k];
#pragma unroll
        for (int i = 0; i < 4; i++)
#pragma unroll
            for (int j = 0; j < 4; j++) acc[i][j] += a[i] * bv[j];
    }
    float b0 = bvec[col0 + tx * 4 + 0];
    float b1 = bvec[col0 + tx * 4 + 1];
    float b2 = bvec[col0 + tx * 4 + 2];
    float b3 = bvec[col0 + tx * 4 + 3];
#pragma unroll
    for (int i = 0; i < 4; i++) {
        int r = row0 + ty * 4 + i;
        float4 v;
        v.x = acc[i][0] + b0;
        v.y = acc[i][1] + b1;
        v.z = acc[i][2] + b2;
        v.w = acc[i][3] + b3;
        *(float4*)(out + (size_t)r * 768 + col0 + tx * 4) = v;
    }
}

// ---------------- launch ---------------------------------------------------
extern "C" void kernel_launch(void* const* d_in, const int* in_sizes, int n_in,
                              void* d_out, int out_size) {
    const float* x         = (const float*)d_in[0];
    const float* ln_gamma  = (const float*)d_in[1];
    const float* ln_beta   = (const float*)d_in[2];
    const float* in_w      = (const float*)d_in[3];
    const float* in_b      = (const float*)d_in[4];
    const float* ext_w     = (const float*)d_in[5];
    const float* ext_scale = (const float*)d_in[6];
    const float* ext_shift = (const float*)d_in[7];
    const float* i0_w      = (const float*)d_in[8];
    const float* i0_scale  = (const float*)d_in[9];
    const float* i0_shift  = (const float*)d_in[10];
    const float* i1_w      = (const float*)d_in[11];
    const float* i1_scale  = (const float*)d_in[12];
    const float* i1_shift  = (const float*)d_in[13];
    const float* i2_w      = (const float*)d_in[14];
    const float* i2_scale  = (const float*)d_in[15];
    const float* i2_shift  = (const float*)d_in[16];
    const float* out_w     = (const float*)d_in[17];
    const float* out_b     = (const float*)d_in[18];
    float* out = (float*)d_out;

    cudaFuncSetAttribute(corr_kernel,      cudaFuncAttributeMaxDynamicSharedMemorySize, 50176);
    cudaFuncSetAttribute(conv64_kernel<0>, cudaFuncAttributeMaxDynamicSharedMemorySize, 102400);
    cudaFuncSetAttribute(conv64_kernel<1>, cudaFuncAttributeMaxDynamicSharedMemorySize, 102400);
    cudaFuncSetAttribute(conv320_kernel,   cudaFuncAttributeMaxDynamicSharedMemorySize, 102400);

    prep_w_kernel<<<64, 256>>>(in_w, ln_gamma, ln_beta, in_b);
    rowstats_kernel<<<3136, 256>>>(x);
    gemm_in_kernel<<<392, 256>>>(x);
    corr_kernel<<<640, 224, 50176>>>();
    ext_kernel<<<dim3(640, 4), 256>>>(ext_w, ext_scale, ext_shift);
    conv64_kernel<0><<<640, 224, 102400>>>(i0_w, i0_scale, i0_shift);
    conv64_kernel<1><<<640, 224, 102400>>>(i1_w, i1_scale, i1_shift);
    conv320_kernel<<<dim3(128, 4), 224, 102400>>>(i2_w, i2_scale, i2_shift);
    transpose_y2_kernel<<<6272, 256>>>();
    gemm_out_kernel<<<dim3(392, 12), 256>>>(out_w, out_b, out);
}

// round 6
// speedup vs baseline: 2.0185x; 2.0185x over previous
#include <cuda_runtime.h>
#include <math.h>

// Problem constants
#define LNUM 196      // H*W
#define BTN  128      // B*T
#define DIM  768
#define NDH  64
#define NT   8
#define NB   16
#define NH   14
#define NLW  5
#define NROWS 25088   // LNUM*BTN
#define NF   640      // B*T*Lw frames
#define PIXC 15876    // 196*81

// ---------------- scratch (device globals: allocation-free) ----------------
__device__ float g_mu[NROWS];
__device__ float g_rstd[NROWS];
__device__ float g_Wg[NDH * DIM];
__device__ float g_A[NDH];
__device__ float g_Bc[NDH];
__device__ float g_fn[BTN * LNUM * NDH];          // normalized features [bt][pix][c]
__device__ float g_corr[(size_t)NF * PIXC];        // [frame][pix][81]
__device__ float g_yext[80 * 64 * 8 * 196];        // [(b*5+l)*64+c][t][pix]
__device__ float g_y0[80 * 64 * 8 * 196];
__device__ float g_y1[80 * 64 * 8 * 196];
__device__ float g_y2[16 * 64 * 8 * 196];          // [(b*64+c)][t][pix]
__device__ float g_y2t[(size_t)NROWS * 64];        // [(pix*128+bt)][c]
// transposed conv weights: [ci][tap][co]
__device__ float g_w0t[64 * 9 * 64];
__device__ float g_w1t[64 * 9 * 64];
__device__ float g_w2t[320 * 9 * 64];

__device__ __forceinline__ float gelu_exact(float x) {
    return 0.5f * x * (1.0f + erff(x * 0.70710678118654752f));
}

// ---------------- kernel 0: fold layernorm gamma/beta into projection ------
__global__ void prep_w_kernel(const float* __restrict__ in_w,
                              const float* __restrict__ gamma,
                              const float* __restrict__ beta,
                              const float* __restrict__ in_b) {
    int c = blockIdx.x;
    int tid = threadIdx.x;
    float pa = 0.f, pb = 0.f;
    for (int d = tid; d < DIM; d += 256) {
        float w  = in_w[c * DIM + d];
        float wg = w * gamma[d];
        g_Wg[c * DIM + d] = wg;
        pa += wg;
        pb += w * beta[d];
    }
    __shared__ float rA[256], rB[256];
    rA[tid] = pa; rB[tid] = pb;
    __syncthreads();
    for (int s = 128; s > 0; s >>= 1) {
        if (tid < s) { rA[tid] += rA[tid + s]; rB[tid] += rB[tid + s]; }
        __syncthreads();
    }
    if (tid == 0) { g_A[c] = rA[0]; g_Bc[c] = rB[0] + in_b[c]; }
}

// ---------------- kernel 0b: transpose conv weights to [ci][tap][co] -------
__global__ void transpose_w_kernel(const float* __restrict__ i0w,
                                   const float* __restrict__ i1w,
                                   const float* __restrict__ i2w) {
    int e = blockIdx.x * 256 + threadIdx.x;
    if (e < 36864) {        // src [co=64][ci=64][9]
        int co = e / 576, r = e % 576, ci = r / 9, tap = r % 9;
        g_w0t[(ci * 9 + tap) * 64 + co] = i0w[e];
        g_w1t[(ci * 9 + tap) * 64 + co] = i1w[e];
    }
    if (e < 184320) {       // src [co=64][ci=320][9]
        int co = e / 2880, r = e % 2880, ci = r / 9, tap = r % 9;
        g_w2t[(ci * 9 + tap) * 64 + co] = i2w[e];
    }
}

// ---------------- kernel 1: per-row LN stats -------------------------------
__global__ void rowstats_kernel(const float* __restrict__ x) {
    int w = threadIdx.x >> 5, lane = threadIdx.x & 31;
    int row = blockIdx.x * 8 + w;
    const float4* p = (const float4*)(x + (size_t)row * DIM);
    float s = 0.f, sq = 0.f;
#pragma unroll
    for (int i = 0; i < 6; i++) {
        float4 v = p[lane + i * 32];
        s  += v.x + v.y + v.z + v.w;
        sq += v.x * v.x + v.y * v.y + v.z * v.z + v.w * v.w;
    }
    for (int o = 16; o > 0; o >>= 1) {
        s  += __shfl_xor_sync(0xffffffffu, s,  o);
        sq += __shfl_xor_sync(0xffffffffu, sq, o);
    }
    if (lane == 0) {
        float mu  = s * (1.0f / DIM);
        float var = sq * (1.0f / DIM) - mu * mu;
        g_mu[row]   = mu;
        g_rstd[row] = rsqrtf(var + 1e-5f);
    }
}

// ---------------- kernel 2: input GEMM + LN epilogue + channel-normalize ---
__global__ void gemm_in_kernel(const float* __restrict__ x) {
    __shared__ float Xs[64][33];
    __shared__ float Ws[64][33];
    __shared__ float Sv[64][65];
    __shared__ float Srow[64][4];
    __shared__ float Sinv[64];
    int tid = threadIdx.x;
    int ty = tid >> 4, tx = tid & 15;
    int row0 = blockIdx.x * 64;
    float acc[4][4] = {};
    for (int kb = 0; kb < DIM; kb += 32) {
#pragma unroll
        for (int i = 0; i < 8; i++) {
            int e = tid + i * 256;
            int r = e >> 5, k = e & 31;
            Xs[r][k] = x[(size_t)(row0 + r) * DIM + kb + k];
            Ws[r][k] = g_Wg[r * DIM + kb + k];
        }
        __syncthreads();
#pragma unroll 8
        for (int k = 0; k < 32; k++) {
            float a[4], b[4];
#pragma unroll
            for (int i = 0; i < 4; i++) a[i] = Xs[ty * 4 + i][k];
#pragma unroll
            for (int j = 0; j < 4; j++) b[j] = Ws[tx * 4 + j][k];
#pragma unroll
            for (int i = 0; i < 4; i++)
#pragma unroll
                for (int j = 0; j < 4; j++) acc[i][j] += a[i] * b[j];
        }
        __syncthreads();
    }
#pragma unroll
    for (int i = 0; i < 4; i++) {
        int r = row0 + ty * 4 + i;
        float rs = g_rstd[r], mu = g_mu[r];
#pragma unroll
        for (int j = 0; j < 4; j++) {
            int c = tx * 4 + j;
            Sv[ty * 4 + i][c] = rs * acc[i][j] - rs * mu * g_A[c] + g_Bc[c];
        }
    }
    __syncthreads();
    {
        int row = tid >> 2, q = tid & 3;
        float s = 0.f;
#pragma unroll
        for (int c = 0; c < 16; c++) { float v = Sv[row][q * 16 + c]; s += v * v; }
        Srow[row][q] = s;
    }
    __syncthreads();
    if (tid < 64) {
        float n = Srow[tid][0] + Srow[tid][1] + Srow[tid][2] + Srow[tid][3];
        Sinv[tid] = 1.0f / fmaxf(sqrtf(n), 1e-7f);
    }
    __syncthreads();
#pragma unroll
    for (int i = 0; i < 16; i++) {
        int e = tid + i * 256;
        int row = e >> 6, c = e & 63;
        int r = row0 + row;
        int l = r >> 7, bt = r & 127;
        g_fn[((size_t)bt * LNUM + l) * NDH + c] = Sv[row][c] * Sinv[row];
    }
}

// ---------------- kernel 3: local 9x9 correlation --------------------------
__global__ void corr_kernel() {
    extern __shared__ float s_tgt[];
    int fidx = blockIdx.x;
    int b = fidx / 40, rem = fidx % 40;
    int t = rem / 5, l = rem % 5;
    int ttg = t + l - 2;
    float* outp = g_corr + (size_t)fidx * PIXC;
    int tid = threadIdx.x;
    if (ttg < 0 || ttg >= NT) {
        for (int e = tid; e < PIXC; e += 224) outp[e] = 0.0f;
        return;
    }
    const float* tgt = g_fn + (size_t)(b * 8 + ttg) * (196 * 64);
    for (int e = tid; e < 3136; e += 224) {
        int p = e >> 4, c4 = e & 15;
        float4 v = *(const float4*)(tgt + p * 64 + c4 * 4);
        s_tgt[(c4 * 4 + 0) * 196 + p] = v.x;
        s_tgt[(c4 * 4 + 1) * 196 + p] = v.y;
        s_tgt[(c4 * 4 + 2) * 196 + p] = v.z;
        s_tgt[(c4 * 4 + 3) * 196 + p] = v.w;
    }
    __syncthreads();
    if (tid < 196) {
        int h = tid / 14, w = tid % 14;
        const float4* src = (const float4*)(g_fn + ((size_t)(b * 8 + t) * 196 + tid) * 64);
        float s[64];
#pragma unroll
        for (int i = 0; i < 16; i++) {
            float4 v = src[i];
            s[i * 4 + 0] = v.x; s[i * 4 + 1] = v.y; s[i * 4 + 2] = v.z; s[i * 4 + 3] = v.w;
        }
        float* op = outp + tid * 81;
#pragma unroll 1
        for (int du = 0; du < 9; du++) {
            int uh = h + du - 4;
            bool rok = (uh >= 0) && (uh < 14);
#pragma unroll 1
            for (int dv = 0; dv < 9; dv++) {
                int vw = w + dv - 4;
                float acc = 0.0f;
                if (rok && vw >= 0 && vw < 14) {
                    const float* tp = s_tgt + uh * 14 + vw;
#pragma unroll
                    for (int c = 0; c < 64; c++) acc += s[c] * tp[c * 196];
                }
                op[du * 9 + dv] = acc;
            }
        }
    }
}

// ---------------- kernel 4: ext 1x1 (81->64) + BN + GELU, 7px x 4co tile ---
// grid (640 frames, 2 pixel-chunks of 98), block 224
__global__ void ext_kernel(const float* __restrict__ ew,
                           const float* __restrict__ scale,
                           const float* __restrict__ shift) {
    extern __shared__ float sm[];
    float* sw = sm;           // [k=81][co=64]  = 5184
    float* sc = sm + 5184;    // [pl=98][k=81]  = 7938
    int fidx = blockIdx.x;
    int pix0 = blockIdx.y * 98;
    int b = fidx / 40, rem = fidx % 40, t = rem / 5, l = rem % 5;
    int tid = threadIdx.x;
    for (int e = tid; e < 5184; e += 224) {
        int k = e >> 6, co = e & 63;
        sw[e] = ew[co * 81 + k];
    }
    const float* cp = g_corr + (size_t)fidx * PIXC + (size_t)pix0 * 81;
    for (int e = tid; e < 7938; e += 224) sc[e] = cp[e];
    __syncthreads();
    int plg = tid >> 4, coq = tid & 15;  // 14 plg x 7 pl, 16 coq x 4 co
    float acc[7][4] = {};
    const float* scp = sc + plg * 7 * 81;
    const float* swp = sw + coq * 4;
#pragma unroll 3
    for (int k = 0; k < 81; k++) {
        float4 wq = *(const float4*)(swp + k * 64);
#pragma unroll
        for (int i = 0; i < 7; i++) {
            float cv = scp[i * 81 + k];
            acc[i][0] += cv * wq.x;
            acc[i][1] += cv * wq.y;
            acc[i][2] += cv * wq.z;
            acc[i][3] += cv * wq.w;
        }
    }
    size_t obase = ((size_t)(b * 5 + l) * 64) * 1568 + (size_t)t * 196 + pix0 + plg * 7;
#pragma unroll
    for (int j = 0; j < 4; j++) {
        int co = coq * 4 + j;
        float scv = scale[co], shv = shift[co];
#pragma unroll
        for (int i = 0; i < 7; i++)
            g_yext[obase + (size_t)co * 1568 + i] = gelu_exact(acc[i][j] * scv + shv);
    }
}

// ---------------- kernels 5/6: 3x3 conv 64->64, row-register tile ----------
// grid 640 (f x t), block 224 = 14 rows x 16 co-groups(4 co each)
// smem: in [32ci][16x16 halo] = 8192 fl, w [32ci][9][64co] = 18432 fl
template <int WHICH>
__global__ void conv64_kernel(const float* __restrict__ scale,
                              const float* __restrict__ shift) {
    extern __shared__ float sm[];
    float* s_in = sm;
    float* s_w  = sm + 8192;
    const float* in = (WHICH == 0) ? g_yext : g_y0;
    const float* Wt = (WHICH == 0) ? g_w0t  : g_w1t;
    float* out      = (WHICH == 0) ? g_y0   : g_y1;
    int f = blockIdx.x >> 3, t = blockIdx.x & 7;
    int tid = threadIdx.x;
    int row = tid >> 4, cog = tid & 15;
    const float* inb = in + (size_t)(f * 512 + t) * 196;
    float acc[14][4] = {};
    for (int cb = 0; cb < 2; cb++) {
        __syncthreads();
        for (int e = tid; e < 8192; e += 224) s_in[e] = 0.0f;
        __syncthreads();
        for (int e = tid; e < 6272; e += 224) {
            int c = e / 196, p = e % 196;
            s_in[c * 256 + ((p / 14) + 1) * 16 + (p % 14) + 1] =
                inb[(size_t)(cb * 32 + c) * 1568 + p];
        }
        for (int e = tid; e < 18432; e += 224)
            s_w[e] = Wt[cb * 18432 + e];
        __syncthreads();
#pragma unroll 1
        for (int ci = 0; ci < 32; ci++) {
            const float* sp = s_in + ci * 256;
            const float* wp = s_w + ci * 576 + cog * 4;
#pragma unroll
            for (int dh = 0; dh < 3; dh++) {
                float win[16];
                const float4* rp = (const float4*)(sp + (row + dh) * 16);
#pragma unroll
                for (int q = 0; q < 4; q++) {
                    float4 v = rp[q];
                    win[q * 4 + 0] = v.x; win[q * 4 + 1] = v.y;
                    win[q * 4 + 2] = v.z; win[q * 4 + 3] = v.w;
                }
#pragma unroll
                for (int dw = 0; dw < 3; dw++) {
                    float4 wq = *(const float4*)(wp + (dh * 3 + dw) * 64);
#pragma unroll
                    for (int px = 0; px < 14; px++) {
                        float iv = win[px + dw];
                        acc[px][0] += iv * wq.x;
                        acc[px][1] += iv * wq.y;
                        acc[px][2] += iv * wq.z;
                        acc[px][3] += iv * wq.w;
                    }
                }
            }
        }
    }
    float* ob = out + (size_t)(f * 512 + t) * 196 + row * 14;
#pragma unroll
    for (int j = 0; j < 4; j++) {
        int co = cog * 4 + j;
        float scv = scale[co], shv = shift[co];
#pragma unroll
        for (int px = 0; px < 14; px++)
            ob[(size_t)co * 1568 + px] = gelu_exact(acc[px][j] * scv + shv);
    }
}

// ---------------- kernel 7: i2 3x3 conv 320->64, row-register tile ---------
// grid (128 slices, 2 co-halves), block 224 = 14 rows x 16 co-groups(2 co)
// smem: in [32ci][16x16] = 8192 fl, w [32ci][9][32co] = 9216 fl
__global__ void conv320_kernel(const float* __restrict__ scale,
                               const float* __restrict__ shift) {
    extern __shared__ float sm[];
    float* s_in = sm;
    float* s_w  = sm + 8192;
    int slice = blockIdx.x;
    int b = slice >> 3, t = slice & 7;
    int coh = blockIdx.y;
    int tid = threadIdx.x;
    int row = tid >> 4, cog = tid & 15;
    float acc[14][2] = {};
    for (int cb = 0; cb < 10; cb++) {
        __syncthreads();
        for (int e = tid; e < 8192; e += 224) s_in[e] = 0.0f;
        __syncthreads();
        for (int e = tid; e < 6272; e += 224) {
            int c = e / 196, p = e % 196;
            s_in[c * 256 + ((p / 14) + 1) * 16 + (p % 14) + 1] =
                g_y1[(size_t)((b * 320 + cb * 32 + c) * 8 + t) * 196 + p];
        }
        for (int e = tid; e < 9216; e += 224) {
            int ci = e / 288, r = e % 288, tap = r >> 5, col = r & 31;
            s_w[e] = g_w2t[((cb * 32 + ci) * 9 + tap) * 64 + coh * 32 + col];
        }
        __syncthreads();
#pragma unroll 1
        for (int ci = 0; ci < 32; ci++) {
            const float* sp = s_in + ci * 256;
            const float* wp = s_w + ci * 288 + cog * 2;
#pragma unroll
            for (int dh = 0; dh < 3; dh++) {
                float win[16];
                const float4* rp = (const float4*)(sp + (row + dh) * 16);
#pragma unroll
                for (int q = 0; q < 4; q++) {
                    float4 v = rp[q];
                    win[q * 4 + 0] = v.x; win[q * 4 + 1] = v.y;
                    win[q * 4 + 2] = v.z; win[q * 4 + 3] = v.w;
                }
#pragma unroll
                for (int dw = 0; dw < 3; dw++) {
                    float2 wq = *(const float2*)(wp + (dh * 3 + dw) * 32);
#pragma unroll
                    for (int px = 0; px < 14; px++) {
                        float iv = win[px + dw];
                        acc[px][0] += iv * wq.x;
                        acc[px][1] += iv * wq.y;
                    }
                }
            }
        }
    }
    float* ob = g_y2 + (size_t)(b * 512 + t) * 196 + row * 14;
#pragma unroll
    for (int j = 0; j < 2; j++) {
        int co = coh * 32 + cog * 2 + j;
        float scv = scale[co], shv = shift[co];
#pragma unroll
        for (int px = 0; px < 14; px++)
            ob[(size_t)co * 1568 + px] = gelu_exact(acc[px][j] * scv + shv);
    }
}

// ---------------- kernel 8: transpose y2 -> row-major [(pix,bt)][c] --------
__global__ void transpose_y2_kernel() {
    int e = blockIdx.x * 256 + threadIdx.x;
    float v = g_y2[e];
    int pix = e % 196;
    int t = (e / 196) & 7;
    int c = (e / 1568) & 63;
    int b = e / (1568 * 64);
    g_y2t[((size_t)(pix * 128 + b * 8 + t)) * 64 + c] = v;
}

// ---------------- kernel 9: output GEMM (25088 x 64 -> 768) + bias ---------
__global__ void gemm_out_kernel(const float* __restrict__ Wo,
                                const float* __restrict__ bvec,
                                float* __restrict__ out) {
    __shared__ float Ys[64][65];
    __shared__ float Wsm[64][65];
    int tid = threadIdx.x;
    int row0 = blockIdx.x * 64, col0 = blockIdx.y * 64;
#pragma unroll
    for (int i = 0; i < 16; i++) {
        int e = tid + i * 256;
        int r = e >> 6, k = e & 63;
        Ys[r][k]  = g_y2t[(size_t)(row0 + r) * 64 + k];
        Wsm[r][k] = Wo[(size_t)(col0 + r) * 64 + k];
    }
    __syncthreads();
    int ty = tid >> 4, tx = tid & 15;
    float acc[4][4] = {};
#pragma unroll 8
    for (int k = 0; k < 64; k++) {
        float a[4], bv[4];
#pragma unroll
        for (int i = 0; i < 4; i++) a[i] = Ys[ty * 4 + i][k];
#pragma unroll
        for (int j = 0; j < 4; j++) bv[j] = Wsm[tx * 4 + j][k];
#pragma unroll
        for (int i = 0; i < 4; i++)
#pragma unroll
            for (int j = 0; j < 4; j++) acc[i][j] += a[i] * bv[j];
    }
    float b0 = bvec[col0 + tx * 4 + 0];
    float b1 = bvec[col0 + tx * 4 + 1];
    float b2 = bvec[col0 + tx * 4 + 2];
    float b3 = bvec[col0 + tx * 4 + 3];
#pragma unroll
    for (int i = 0; i < 4; i++) {
        int r = row0 + ty * 4 + i;
        float4 v;
        v.x = acc[i][0] + b0;
        v.y = acc[i][1] + b1;
        v.z = acc[i][2] + b2;
        v.w = acc[i][3] + b3;
        *(float4*)(out + (size_t)r * 768 + col0 + tx * 4) = v;
    }
}

// ---------------- launch ---------------------------------------------------
extern "C" void kernel_launch(void* const* d_in, const int* in_sizes, int n_in,
                              void* d_out, int out_size) {
    const float* x         = (const float*)d_in[0];
    const float* ln_gamma  = (const float*)d_in[1];
    const float* ln_beta   = (const float*)d_in[2];
    const float* in_w      = (const float*)d_in[3];
    const float* in_b      = (const float*)d_in[4];
    const float* ext_w     = (const float*)d_in[5];
    const float* ext_scale = (const float*)d_in[6];
    const float* ext_shift = (const float*)d_in[7];
    const float* i0_w      = (const float*)d_in[8];
    const float* i0_scale  = (const float*)d_in[9];
    const float* i0_shift  = (const float*)d_in[10];
    const float* i1_w      = (const float*)d_in[11];
    const float* i1_scale  = (const float*)d_in[12];
    const float* i1_shift  = (const float*)d_in[13];
    const float* i2_w      = (const float*)d_in[14];
    const float* i2_scale  = (const float*)d_in[15];
    const float* i2_shift  = (const float*)d_in[16];
    const float* out_w     = (const float*)d_in[17];
    const float* out_b     = (const float*)d_in[18];
    float* out = (float*)d_out;

    cudaFuncSetAttribute(corr_kernel,      cudaFuncAttributeMaxDynamicSharedMemorySize, 50176);
    cudaFuncSetAttribute(ext_kernel,       cudaFuncAttributeMaxDynamicSharedMemorySize, 52488);
    cudaFuncSetAttribute(conv64_kernel<0>, cudaFuncAttributeMaxDynamicSharedMemorySize, 106496);
    cudaFuncSetAttribute(conv64_kernel<1>, cudaFuncAttributeMaxDynamicSharedMemorySize, 106496);
    cudaFuncSetAttribute(conv320_kernel,   cudaFuncAttributeMaxDynamicSharedMemorySize, 69632);

    prep_w_kernel<<<64, 256>>>(in_w, ln_gamma, ln_beta, in_b);
    transpose_w_kernel<<<720, 256>>>(i0_w, i1_w, i2_w);
    rowstats_kernel<<<3136, 256>>>(x);
    gemm_in_kernel<<<392, 256>>>(x);
    corr_kernel<<<640, 224, 50176>>>();
    ext_kernel<<<dim3(640, 2), 224, 52488>>>(ext_w, ext_scale, ext_shift);
    conv64_kernel<0><<<640, 224, 106496>>>(i0_scale, i0_shift);
    conv64_kernel<1><<<640, 224, 106496>>>(i1_scale, i1_shift);
    conv320_kernel<<<dim3(128, 2), 224, 69632>>>(i2_scale, i2_shift);
    transpose_y2_kernel<<<6272, 256>>>();
    gemm_out_kernel<<<dim3(392, 12), 256>>>(out_w, out_b, out);
}